// round 16
// baseline (speedup 1.0000x reference)
#include <cuda_runtime.h>
#include <cstdint>

#define FULLMASK 0xFFFFFFFFu
#define MAXC  16
#define BMAX  4096
#define NS    128
#define HROWS 64
#define PROWS 16
#define KMAXC 128
#define PW    128

#define PST 132   // P row stride: B-frag banks (4t+g+8nt) distinct -> clean

// X tile stored swizzled: addr(r,c) = r*128 + ((c + 4r) & 127)
#define XIDX(r, c) (((r) << 7) + (((c) + 4 * (r)) & 127))

// smem floats: Xs[64*128] | Pchunk[16*132] | xtop[64*4*5]
#define OFF_X    0
#define OFF_P    (HROWS * KMAXC)                  // 8192
#define OFF_XTOP (OFF_P + PROWS * PST)            // 10304
#define SMEM_FLOATS (OFF_XTOP + HROWS * 4 * 5)    // 11584 -> 46336 B (5 CTA/SM)
// ctop[64 rows][8 slots][5] = 2560 floats aliases the dead X tile (8192)
#define OFF_CTOP OFF_X

__device__ int      d_gid[BMAX];
__device__ int      d_pos[BMAX];
__device__ int      d_cn[MAXC];
__device__ int      d_ck[MAXC];
__device__ int      d_cm[MAXC];
__device__ unsigned d_key0[MAXC];
__device__ unsigned d_key1[MAXC];
__device__ int      d_gsz[MAXC];
__device__ int      d_val[MAXC];
__device__ unsigned d_hm[BMAX];   // per-b max_hm as float bits (nonneg)

// TF32 round-to-nearest-even (applied to P at staging)
__device__ __forceinline__ float tf32_rne(float x) {
  unsigned u = __float_as_uint(x);
  u = (u + 0xFFFu + ((u >> 13) & 1u)) & 0xFFFFE000u;
  return __uint_as_float(u);
}

// m16n8k8 tf32 mma (sm_80 PTX; fallback HMMA on sm_103)
__device__ __forceinline__ void mma_tf32(float* c, uint32_t a0, uint32_t a1,
                                         uint32_t a2, uint32_t a3,
                                         uint32_t b0, uint32_t b1) {
  asm volatile(
    "mma.sync.aligned.m16n8k8.row.col.f32.tf32.tf32.f32 "
    "{%0,%1,%2,%3}, {%4,%5,%6,%7}, {%8,%9}, {%0,%1,%2,%3};"
    : "+f"(c[0]), "+f"(c[1]), "+f"(c[2]), "+f"(c[3])
    : "r"(a0), "r"(a1), "r"(a2), "r"(a3), "r"(b0), "r"(b1));
}

// JAX threefry2x32-20 (KAT-verified)
__device__ __forceinline__ void threefry2x32(unsigned k0, unsigned k1,
                                             unsigned &x0, unsigned &x1) {
  unsigned k2 = k0 ^ k1 ^ 0x1BD11BDAu;
  x0 += k0; x1 += k1;
#define TFR(d) { x0 += x1; x1 = __funnelshift_l(x1, x1, (d)); x1 ^= x0; }
  TFR(13) TFR(15) TFR(26) TFR(6)
  x0 += k1; x1 += k2 + 1u;
  TFR(17) TFR(29) TFR(16) TFR(24)
  x0 += k2; x1 += k0 + 2u;
  TFR(13) TFR(15) TFR(26) TFR(6)
  x0 += k0; x1 += k1 + 3u;
  TFR(17) TFR(29) TFR(16) TFR(24)
  x0 += k1; x1 += k2 + 4u;
  TFR(13) TFR(15) TFR(26) TFR(6)
  x0 += k2; x1 += k0 + 5u;
#undef TFR
}

// XLA ErfInv32 (Giles); log1p(-x*x) -> -__logf(1-x*x), induced err ~1e-7 rel
__device__ __forceinline__ float erfinv_xla(float x) {
  float xx = x * x;
  float w = -__logf(1.0f - xx);
  float p;
  if (w < 5.0f) {
    w -= 2.5f;
    p = 2.81022636e-08f;
    p = fmaf(p, w, 3.43273939e-07f);
    p = fmaf(p, w, -3.5233877e-06f);
    p = fmaf(p, w, -4.39150654e-06f);
    p = fmaf(p, w, 0.00021858087f);
    p = fmaf(p, w, -0.00125372503f);
    p = fmaf(p, w, -0.00417768164f);
    p = fmaf(p, w, 0.246640727f);
    p = fmaf(p, w, 1.50140941f);
  } else {
    w = sqrtf(w) - 3.0f;
    p = -0.000200214257f;
    p = fmaf(p, w, 0.000100950558f);
    p = fmaf(p, w, 0.00134934322f);
    p = fmaf(p, w, -0.00367342844f);
    p = fmaf(p, w, 0.00573950773f);
    p = fmaf(p, w, -0.0076224613f);
    p = fmaf(p, w, 0.00943887047f);
    p = fmaf(p, w, 1.00167406f);
    p = fmaf(p, w, 2.83297682f);
  }
  return p * x;
}

// one JAX normal (partitionable threefry: ctr (0, ge); out = x0^x1)
__device__ __forceinline__ float gen_normal(unsigned key0, unsigned key1,
                                            unsigned ge) {
  unsigned x0 = 0u, x1 = ge;
  threefry2x32(key0, key1, x0, x1);
  unsigned bits = x0 ^ x1;
  float f = __uint_as_float((bits >> 9) | 0x3F800000u) - 1.0f;
  float u = fmaf(f, 2.0f, -0.99999994f);
  u = fmaxf(-0.99999994f, u);
  return 1.41421356f * erfinv_xla(u);
}

__device__ __forceinline__ unsigned enc_params(const int* p, int b, int stride) {
  unsigned n = (unsigned)p[(3*b + 0) * stride];
  unsigned k = (unsigned)p[(3*b + 1) * stride];
  unsigned m = (unsigned)p[(3*b + 2) * stride];
  return (n << 20) | ((k & 1023u) << 10) | (m & 1023u);
}

// np.unique(params, axis=0, return_inverse) replication + positions/keys.
__global__ void prep_kernel(const int* __restrict__ params, int B, int stride) {
  const int T = 256;
  int tid = threadIdx.x;
  __shared__ unsigned enc[MAXC];
  __shared__ unsigned senc[MAXC];
  __shared__ int nc_s;
  __shared__ unsigned eb[BMAX];
  __shared__ unsigned char gb[BMAX];
  __shared__ unsigned short cnt[256][MAXC];
  if (tid < MAXC) enc[tid] = 0xFFFFFFFFu;
#pragma unroll
  for (int j = 0; j < MAXC; j++) cnt[tid][j] = 0;
  if (tid == 0) nc_s = 0;
  for (int i = tid; i < B; i += T) d_hm[i] = 0u;
  __syncthreads();

  int chunk = (B + T - 1) / T;
  int b0 = tid * chunk;
  int b1 = min(B, b0 + chunk);

  {
    unsigned seen[8]; int ns = 0;
    for (int b = b0; b < b1; b++) {
      unsigned e = enc_params(params, b, stride);
      eb[b] = e;
      bool dup = false;
#pragma unroll
      for (int i = 0; i < 8; i++) if (i < ns && seen[i] == e) dup = true;
      if (dup) continue;
      if (ns < 8) seen[ns++] = e;
      for (int j = 0; j < MAXC; j++) {
        unsigned cur = enc[j];
        if (cur == e) break;
        if (cur == 0xFFFFFFFFu) {
          unsigned old = atomicCAS(&enc[j], 0xFFFFFFFFu, e);
          if (old == 0xFFFFFFFFu || old == e) break;
        }
      }
    }
  }
  __syncthreads();

  if (tid == 0) {
    int nc = 0;
    while (nc < MAXC && enc[nc] != 0xFFFFFFFFu) nc++;
    for (int i = 0; i < nc; i++) {
      int bi = i; unsigned best = enc[i];
      for (int j = i + 1; j < nc; j++) if (enc[j] < best) { best = enc[j]; bi = j; }
      unsigned t = enc[i]; enc[i] = enc[bi]; enc[bi] = t;
    }
    for (int i = 0; i < nc; i++) senc[i] = enc[i];
    nc_s = nc;
  }
  __syncthreads();
  int nc = nc_s;

  unsigned se[MAXC];
#pragma unroll
  for (int j = 0; j < MAXC; j++) se[j] = (j < nc) ? senc[j] : 0xFFFFFFFFu;

  for (int b = b0; b < b1; b++) {
    unsigned e = eb[b];
    int g = 0;
#pragma unroll
    for (int j = 0; j < MAXC; j++) if (se[j] == e) g = j;
    gb[b] = (unsigned char)g;
    cnt[tid][g]++;
  }
  __syncthreads();

  if (tid < MAXC) {
    int run = 0;
    for (int c = 0; c < T; c++) {
      int t = cnt[c][tid];
      cnt[c][tid] = (unsigned short)run;
      run += t;
    }
    d_gsz[tid] = run;
  }
  __syncthreads();

  for (int b = b0; b < b1; b++) {
    int g = (int)gb[b];
    d_gid[b] = g;
    d_pos[b] = cnt[tid][g]++;
  }

  if (tid < MAXC) {
    if (tid < nc) {
      unsigned e = senc[tid];
      int n = (int)(e >> 20), k = (int)((e >> 10) & 1023u), m = (int)(e & 1023u);
      d_cn[tid] = n; d_ck[tid] = k; d_cm[tid] = m;
      unsigned x0 = 0u, x1 = (unsigned)tid;      // fold_in(key(42), i)
      threefry2x32(0u, 42u, x0, x1);
      d_key0[tid] = x0; d_key1[tid] = x1;
      int gsz = d_gsz[tid];
      d_val[tid] = (m + 1 <= n) && (k > 0) && (n - k >= 0) && (gsz > 0) &&
                   (k <= KMAXC) && (n - k <= PW) && (m <= 4) ? 1 : 0;
    } else {
      d_val[tid] = 0;
    }
  }
}

// guarded top-5 insert (skip full network when v <= current 5th)
#define INSG(vv) { float _v = (vv); if (_v > t4) {            \
  float _m;                                                   \
  _m=fmaxf(t0,_v); _v=fminf(t0,_v); t0=_m;                    \
  _m=fmaxf(t1,_v); _v=fminf(t1,_v); t1=_m;                    \
  _m=fmaxf(t2,_v); _v=fminf(t2,_v); t2=_m;                    \
  _m=fmaxf(t3,_v); _v=fminf(t3,_v); t3=_m;                    \
  t4=fmaxf(t4,_v); } }

// two CTAs per batch element (64 rows each); 256 threads; mma.sync tf32 GEMM;
// P staged in 16-k-row chunks; swizzled X tile -> 46336 B smem -> 5 CTAs/SM.
__global__ void __launch_bounds__(256, 5)
main_kernel(const float* __restrict__ P_padded, int B) {
  int b = blockIdx.x >> 1;
  int h = blockIdx.x & 1;
  int tid = threadIdx.x;
  if (b >= B) return;
  int gid = d_gid[b];
  if (!d_val[gid]) return;           // d_hm stays 0 -> penalty 0

  int k = d_ck[gid], m = d_cm[gid];
  int nk = d_cn[gid] - k; if (nk > PW) nk = PW;
  int k8 = (k + 7) & ~7;
  unsigned key0 = d_key0[gid], key1 = d_key1[gid];
  unsigned base = (unsigned)d_pos[b] * (unsigned)(NS * k);

  extern __shared__ float smem[];
  float* Xs   = smem + OFF_X;
  float* Ps   = smem + OFF_P;
  float* xtop = smem + OFF_XTOP;
  float* ctop = smem + OFF_CTOP;     // aliases dead X tile after GEMM

  // ---- X generation: 4 threads per row; 4 independent threefry chains per
  // batch (ILP), one STS.128 per batch; swizzled placement.
  {
    int row = tid >> 2;          // 0..63
    int q   = tid & 3;
    int kq  = k8 >> 2;           // multiple of 4 for all dataset k
    unsigned rbase = base + (unsigned)((h * HROWS + row) * k);
    float t0 = 0.f, t1 = 0.f, t2 = 0.f, t3 = 0.f, t4 = 0.f;
    for (int j0 = 0; j0 < kq; j0 += 4) {
      float v0, v1, v2, v3;
      int c0 = q * kq + j0;
      v0 = (c0 + 0 < k) ? gen_normal(key0, key1, rbase + (unsigned)(c0 + 0)) : 0.f;
      v1 = (c0 + 1 < k) ? gen_normal(key0, key1, rbase + (unsigned)(c0 + 1)) : 0.f;
      v2 = (c0 + 2 < k) ? gen_normal(key0, key1, rbase + (unsigned)(c0 + 2)) : 0.f;
      v3 = (c0 + 3 < k) ? gen_normal(key0, key1, rbase + (unsigned)(c0 + 3)) : 0.f;
      INSG(fabsf(v0)) INSG(fabsf(v1)) INSG(fabsf(v2)) INSG(fabsf(v3))
      *(float4*)(Xs + XIDX(row, c0)) = make_float4(v0, v1, v2, v3);
    }
    float* xt = xtop + (row * 4 + q) * 5;
    xt[0] = t0; xt[1] = t1; xt[2] = t2; xt[3] = t3; xt[4] = t4;
  }

  // ---- GEMM over 16-k-row chunks ----
  int lane = tid & 31;
  int warp = tid >> 5;
  int mtile = warp >> 1;           // rows mtile*16..+15
  int nhalf = warp & 1;            // cols nhalf*64..+63
  int r0 = mtile * 16;
  int n0 = nhalf * 64;
  int g = lane >> 2;
  int t = lane & 3;

  float acc[8][4];
#pragma unroll
  for (int nt = 0; nt < 8; nt++)
#pragma unroll
    for (int j = 0; j < 4; j++) acc[nt][j] = 0.f;

  const uint32_t* Xu = (const uint32_t*)Xs;
  const uint32_t* Pu = (const uint32_t*)Ps;
  const float4* Pb4 = (const float4*)(P_padded + (size_t)b * (KMAXC * PW));
  int rA0 = r0 + g;
  int rA1 = r0 + g + 8;
  int xb0 = rA0 << 7;              // row base for swizzled X
  int xb1 = rA1 << 7;
  int xo0 = 4 * rA0;               // swizzle offsets
  int xo1 = 4 * rA1;

  int nchunks = k8 >> 4;
  for (int c = 0; c < nchunks; c++) {
    int kbase = c * PROWS;
    // stage P rows [kbase, kbase+16), TF32-rounded, zero-padded
    {
      for (int i = tid; i < PROWS * 32; i += 256) {
        int r = i >> 5, c4 = i & 31, col = c4 * 4;
        int gr = kbase + r;
        float4 v = make_float4(0.f, 0.f, 0.f, 0.f);
        if (gr < k) {
          v = Pb4[gr * 32 + c4];
          v.x = (col + 0 < nk) ? tf32_rne(v.x) : 0.f;
          v.y = (col + 1 < nk) ? tf32_rne(v.y) : 0.f;
          v.z = (col + 2 < nk) ? tf32_rne(v.z) : 0.f;
          v.w = (col + 3 < nk) ? tf32_rne(v.w) : 0.f;
        }
        *(float4*)(Ps + r * PST + col) = v;
      }
    }
    __syncthreads();   // X (c==0) + P chunk ready; prior mma reads done

#pragma unroll
    for (int s = 0; s < 2; s++) {
      int kc = s * 8;           // local within chunk
      int gk = kbase + kc;      // global k col for A
      uint32_t a0 = Xu[xb0 + ((gk + t     + xo0) & 127)];
      uint32_t a1 = Xu[xb1 + ((gk + t     + xo1) & 127)];
      uint32_t a2 = Xu[xb0 + ((gk + t + 4 + xo0) & 127)];
      uint32_t a3 = Xu[xb1 + ((gk + t + 4 + xo1) & 127)];
      int pb0 = (kc + t) * PST + n0 + g;
      int pb1 = (kc + t + 4) * PST + n0 + g;
#pragma unroll
      for (int nt = 0; nt < 8; nt++) {
        uint32_t b0 = Pu[pb0 + nt * 8];
        uint32_t b1 = Pu[pb1 + nt * 8];
        mma_tf32(acc[nt], a0, a1, a2, a3, b0, b1);
      }
    }
    __syncthreads();   // mma reads done before restage
  }

  // ---- per-lane C top-5 for its two rows -> ctop (aliases dead X) ----
  {
    int slot = nhalf * 4 + t;
    { float t0 = 0.f, t1 = 0.f, t2 = 0.f, t3 = 0.f, t4 = 0.f;
#pragma unroll
      for (int nt = 0; nt < 8; nt++) { INSG(fabsf(acc[nt][0])) INSG(fabsf(acc[nt][1])) }
      float* c0p = ctop + (rA0 * 8 + slot) * 5;
      c0p[0]=t0; c0p[1]=t1; c0p[2]=t2; c0p[3]=t3; c0p[4]=t4; }
    { float t0 = 0.f, t1 = 0.f, t2 = 0.f, t3 = 0.f, t4 = 0.f;
#pragma unroll
      for (int nt = 0; nt < 8; nt++) { INSG(fabsf(acc[nt][2])) INSG(fabsf(acc[nt][3])) }
      float* c1p = ctop + (rA1 * 8 + slot) * 5;
      c1p[0]=t0; c1p[1]=t1; c1p[2]=t2; c1p[3]=t3; c1p[4]=t4; }
  }
  __syncthreads();

  // ---- merge per row (threads 0..63): 8 C-lists + 4 X-lists -> hm ----
  if (tid < 64) {
    float t0 = 0.f, t1 = 0.f, t2 = 0.f, t3 = 0.f, t4 = 0.f;
    const float* cr = ctop + tid * 8 * 5;
#pragma unroll
    for (int j = 0; j < 40; j++) INSG(cr[j])
    const float* xr = xtop + tid * 4 * 5;
#pragma unroll
    for (int j = 0; j < 20; j++) INSG(xr[j])
    float gm = (m <= 0) ? t0 : (m == 1) ? t1 : (m == 2) ? t2
             : (m == 3) ? t3 : t4;
    float hm = t0 / (gm + 1e-9f);
    unsigned mx = __reduce_max_sync(FULLMASK, __float_as_uint(hm));
    if (lane == 0) atomicMax(&d_hm[b], mx);   // nonneg: uint order == float
  }
}

__global__ void final_kernel(const float* __restrict__ y_pred,
                             const float* __restrict__ y_true,
                             int B, float* __restrict__ out) {
  __shared__ float s1[512], s2[512];
  int tid = threadIdx.x;
  float a = 0.f, v = 0.f;
  for (int b = tid; b < B; b += 512) {
    float lp = log2f(fmaxf(y_pred[b], 1e-9f));
    float lt = log2f(fmaxf(y_true[b], 1e-9f));
    float d = lt - lp;
    a += d * d;
    v += fmaxf(__uint_as_float(d_hm[b]) - y_pred[b], 0.0f);
  }
  s1[tid] = a; s2[tid] = v;
  __syncthreads();
  for (int s = 256; s > 0; s >>= 1) {
    if (tid < s) { s1[tid] += s1[tid + s]; s2[tid] += s2[tid + s]; }
    __syncthreads();
  }
  if (tid == 0) {
    float logmse = s1[0] / (float)B;
    float viol   = s2[0] / (float)B;
    out[0] = logmse + 0.5f * viol;
    out[1] = logmse;
    out[2] = viol;
  }
}

extern "C" void kernel_launch(void* const* d_in, const int* in_sizes, int n_in,
                              void* d_out, int out_size) {
  const float* y_pred   = (const float*)d_in[0];
  const float* y_true   = (const float*)d_in[1];
  const float* P_padded = (const float*)d_in[2];
  const int*   params   = (const int*)d_in[3];
  float* out = (float*)d_out;
  int B = in_sizes[0];
  int stride = (in_sizes[3] >= B * 3 * 2) ? 2 : 1;   // int64 params

  int smem_bytes = SMEM_FLOATS * (int)sizeof(float);   // 46336 B
  cudaFuncSetAttribute(main_kernel,
                       cudaFuncAttributeMaxDynamicSharedMemorySize, smem_bytes);

  prep_kernel<<<1, 256>>>(params, B, stride);
  main_kernel<<<B * 2, 256, smem_bytes>>>(P_padded, B);
  final_kernel<<<1, 512>>>(y_pred, y_true, B, out);
  (void)n_in; (void)out_size;
}

// round 17
// speedup vs baseline: 1.1252x; 1.1252x over previous
#include <cuda_runtime.h>
#include <cstdint>

#define FULLMASK 0xFFFFFFFFu
#define MAXC  16
#define BMAX  4096
#define NS    128
#define PROWS 32
#define KMAXC 128
#define PW    128
#define NT    512

#define XST 132   // Xs row stride (floats): A-frag loads conflict-free
#define PST 136   // Ps row stride (floats): B-frag loads conflict-free

// smem floats: Xs[128*132] | Pchunk[32*136] | xtop[128*4*5]
#define OFF_X    0
#define OFF_P    (NS * XST)                       // 16896
#define OFF_XTOP (OFF_P + PROWS * PST)            // 21248
#define SMEM_FLOATS (OFF_XTOP + NS * 4 * 5)       // 23808 -> 95232 B (2 CTA/SM,
                                                  //  32 warps/SM)
// ctop[128 rows][8 slots][5] = 5120 floats aliases the dead X tile (16896)
#define OFF_CTOP OFF_X

__device__ int      d_gid[BMAX];
__device__ int      d_pos[BMAX];
__device__ int      d_cn[MAXC];
__device__ int      d_ck[MAXC];
__device__ int      d_cm[MAXC];
__device__ unsigned d_key0[MAXC];
__device__ unsigned d_key1[MAXC];
__device__ int      d_gsz[MAXC];
__device__ int      d_val[MAXC];
__device__ unsigned d_hm[BMAX];   // per-b max_hm as float bits (nonneg)

// TF32 round-to-nearest-even (applied to P at staging)
__device__ __forceinline__ float tf32_rne(float x) {
  unsigned u = __float_as_uint(x);
  u = (u + 0xFFFu + ((u >> 13) & 1u)) & 0xFFFFE000u;
  return __uint_as_float(u);
}

// m16n8k8 tf32 mma (sm_80 PTX; fallback HMMA on sm_103)
__device__ __forceinline__ void mma_tf32(float* c, uint32_t a0, uint32_t a1,
                                         uint32_t a2, uint32_t a3,
                                         uint32_t b0, uint32_t b1) {
  asm volatile(
    "mma.sync.aligned.m16n8k8.row.col.f32.tf32.tf32.f32 "
    "{%0,%1,%2,%3}, {%4,%5,%6,%7}, {%8,%9}, {%0,%1,%2,%3};"
    : "+f"(c[0]), "+f"(c[1]), "+f"(c[2]), "+f"(c[3])
    : "r"(a0), "r"(a1), "r"(a2), "r"(a3), "r"(b0), "r"(b1));
}

// JAX threefry2x32-20 (KAT-verified)
__device__ __forceinline__ void threefry2x32(unsigned k0, unsigned k1,
                                             unsigned &x0, unsigned &x1) {
  unsigned k2 = k0 ^ k1 ^ 0x1BD11BDAu;
  x0 += k0; x1 += k1;
#define TFR(d) { x0 += x1; x1 = __funnelshift_l(x1, x1, (d)); x1 ^= x0; }
  TFR(13) TFR(15) TFR(26) TFR(6)
  x0 += k1; x1 += k2 + 1u;
  TFR(17) TFR(29) TFR(16) TFR(24)
  x0 += k2; x1 += k0 + 2u;
  TFR(13) TFR(15) TFR(26) TFR(6)
  x0 += k0; x1 += k1 + 3u;
  TFR(17) TFR(29) TFR(16) TFR(24)
  x0 += k1; x1 += k2 + 4u;
  TFR(13) TFR(15) TFR(26) TFR(6)
  x0 += k2; x1 += k0 + 5u;
#undef TFR
}

// XLA ErfInv32 (Giles); log1p(-x*x) -> -__logf(1-x*x), induced err ~1e-7 rel
__device__ __forceinline__ float erfinv_xla(float x) {
  float xx = x * x;
  float w = -__logf(1.0f - xx);
  float p;
  if (w < 5.0f) {
    w -= 2.5f;
    p = 2.81022636e-08f;
    p = fmaf(p, w, 3.43273939e-07f);
    p = fmaf(p, w, -3.5233877e-06f);
    p = fmaf(p, w, -4.39150654e-06f);
    p = fmaf(p, w, 0.00021858087f);
    p = fmaf(p, w, -0.00125372503f);
    p = fmaf(p, w, -0.00417768164f);
    p = fmaf(p, w, 0.246640727f);
    p = fmaf(p, w, 1.50140941f);
  } else {
    w = sqrtf(w) - 3.0f;
    p = -0.000200214257f;
    p = fmaf(p, w, 0.000100950558f);
    p = fmaf(p, w, 0.00134934322f);
    p = fmaf(p, w, -0.00367342844f);
    p = fmaf(p, w, 0.00573950773f);
    p = fmaf(p, w, -0.0076224613f);
    p = fmaf(p, w, 0.00943887047f);
    p = fmaf(p, w, 1.00167406f);
    p = fmaf(p, w, 2.83297682f);
  }
  return p * x;
}

// one JAX normal (partitionable threefry: ctr (0, ge); out = x0^x1)
__device__ __forceinline__ float gen_normal(unsigned key0, unsigned key1,
                                            unsigned ge) {
  unsigned x0 = 0u, x1 = ge;
  threefry2x32(key0, key1, x0, x1);
  unsigned bits = x0 ^ x1;
  float f = __uint_as_float((bits >> 9) | 0x3F800000u) - 1.0f;
  float u = fmaf(f, 2.0f, -0.99999994f);
  u = fmaxf(-0.99999994f, u);
  return 1.41421356f * erfinv_xla(u);
}

__device__ __forceinline__ unsigned enc_params(const int* p, int b, int stride) {
  unsigned n = (unsigned)p[(3*b + 0) * stride];
  unsigned k = (unsigned)p[(3*b + 1) * stride];
  unsigned m = (unsigned)p[(3*b + 2) * stride];
  return (n << 20) | ((k & 1023u) << 10) | (m & 1023u);
}

// np.unique(params, axis=0, return_inverse) replication + positions/keys.
__global__ void prep_kernel(const int* __restrict__ params, int B, int stride) {
  const int T = 256;
  int tid = threadIdx.x;
  __shared__ unsigned enc[MAXC];
  __shared__ unsigned senc[MAXC];
  __shared__ int nc_s;
  __shared__ unsigned eb[BMAX];
  __shared__ unsigned char gb[BMAX];
  __shared__ unsigned short cnt[256][MAXC];
  if (tid < MAXC) enc[tid] = 0xFFFFFFFFu;
#pragma unroll
  for (int j = 0; j < MAXC; j++) cnt[tid][j] = 0;
  if (tid == 0) nc_s = 0;
  for (int i = tid; i < B; i += T) d_hm[i] = 0u;
  __syncthreads();

  int chunk = (B + T - 1) / T;
  int b0 = tid * chunk;
  int b1 = min(B, b0 + chunk);

  {
    unsigned seen[8]; int ns = 0;
    for (int b = b0; b < b1; b++) {
      unsigned e = enc_params(params, b, stride);
      eb[b] = e;
      bool dup = false;
#pragma unroll
      for (int i = 0; i < 8; i++) if (i < ns && seen[i] == e) dup = true;
      if (dup) continue;
      if (ns < 8) seen[ns++] = e;
      for (int j = 0; j < MAXC; j++) {
        unsigned cur = enc[j];
        if (cur == e) break;
        if (cur == 0xFFFFFFFFu) {
          unsigned old = atomicCAS(&enc[j], 0xFFFFFFFFu, e);
          if (old == 0xFFFFFFFFu || old == e) break;
        }
      }
    }
  }
  __syncthreads();

  if (tid == 0) {
    int nc = 0;
    while (nc < MAXC && enc[nc] != 0xFFFFFFFFu) nc++;
    for (int i = 0; i < nc; i++) {
      int bi = i; unsigned best = enc[i];
      for (int j = i + 1; j < nc; j++) if (enc[j] < best) { best = enc[j]; bi = j; }
      unsigned t = enc[i]; enc[i] = enc[bi]; enc[bi] = t;
    }
    for (int i = 0; i < nc; i++) senc[i] = enc[i];
    nc_s = nc;
  }
  __syncthreads();
  int nc = nc_s;

  unsigned se[MAXC];
#pragma unroll
  for (int j = 0; j < MAXC; j++) se[j] = (j < nc) ? senc[j] : 0xFFFFFFFFu;

  for (int b = b0; b < b1; b++) {
    unsigned e = eb[b];
    int g = 0;
#pragma unroll
    for (int j = 0; j < MAXC; j++) if (se[j] == e) g = j;
    gb[b] = (unsigned char)g;
    cnt[tid][g]++;
  }
  __syncthreads();

  if (tid < MAXC) {
    int run = 0;
    for (int c = 0; c < T; c++) {
      int t = cnt[c][tid];
      cnt[c][tid] = (unsigned short)run;
      run += t;
    }
    d_gsz[tid] = run;
  }
  __syncthreads();

  for (int b = b0; b < b1; b++) {
    int g = (int)gb[b];
    d_gid[b] = g;
    d_pos[b] = cnt[tid][g]++;
  }

  if (tid < MAXC) {
    if (tid < nc) {
      unsigned e = senc[tid];
      int n = (int)(e >> 20), k = (int)((e >> 10) & 1023u), m = (int)(e & 1023u);
      d_cn[tid] = n; d_ck[tid] = k; d_cm[tid] = m;
      unsigned x0 = 0u, x1 = (unsigned)tid;      // fold_in(key(42), i)
      threefry2x32(0u, 42u, x0, x1);
      d_key0[tid] = x0; d_key1[tid] = x1;
      int gsz = d_gsz[tid];
      d_val[tid] = (m + 1 <= n) && (k > 0) && (n - k >= 0) && (gsz > 0) &&
                   (k <= KMAXC) && (n - k <= PW) && (m <= 4) ? 1 : 0;
    } else {
      d_val[tid] = 0;
    }
  }
}

// guarded top-5 insert (skip full network when v <= current 5th)
#define INSG(vv) { float _v = (vv); if (_v > t4) {            \
  float _m;                                                   \
  _m=fmaxf(t0,_v); _v=fminf(t0,_v); t0=_m;                    \
  _m=fmaxf(t1,_v); _v=fminf(t1,_v); t1=_m;                    \
  _m=fmaxf(t2,_v); _v=fminf(t2,_v); t2=_m;                    \
  _m=fmaxf(t3,_v); _v=fminf(t3,_v); t3=_m;                    \
  t4=fmaxf(t4,_v); } }

// ONE 512-thread CTA per batch element (all 128 rows); 16 warps;
// mma.sync tf32 GEMM, P staged ONCE per b in four 32-k-row chunks.
// 95232 B smem -> 2 CTAs/SM = 32 warps/SM (same as R15, half the P work).
__global__ void __launch_bounds__(NT, 2)
main_kernel(const float* __restrict__ P_padded, int B) {
  int b = blockIdx.x;
  int tid = threadIdx.x;
  if (b >= B) return;
  int gid = d_gid[b];
  if (!d_val[gid]) return;           // d_hm stays 0 -> penalty 0

  int k = d_ck[gid], m = d_cm[gid];
  int nk = d_cn[gid] - k; if (nk > PW) nk = PW;
  int k8 = (k + 7) & ~7;
  unsigned key0 = d_key0[gid], key1 = d_key1[gid];
  unsigned base = (unsigned)d_pos[b] * (unsigned)(NS * k);

  extern __shared__ float smem[];
  float* Xs   = smem + OFF_X;
  float* Ps   = smem + OFF_P;
  float* xtop = smem + OFF_XTOP;
  float* ctop = smem + OFF_CTOP;     // aliases dead X tile after GEMM

  // ---- X generation: 4 threads per row; 4 independent threefry chains per
  // iteration (ILP), one STS.128 per batch.
  {
    int row = tid >> 2;          // 0..127
    int q   = tid & 3;
    int kq  = k8 >> 2;           // multiple of 4 for all dataset k
    unsigned rbase = base + (unsigned)(row * k);
    float t0 = 0.f, t1 = 0.f, t2 = 0.f, t3 = 0.f, t4 = 0.f;
    float* Xrow = Xs + row * XST + q * kq;
    for (int j0 = 0; j0 < kq; j0 += 4) {
      float v0, v1, v2, v3;
      int c0 = q * kq + j0;
      v0 = (c0 + 0 < k) ? gen_normal(key0, key1, rbase + (unsigned)(c0 + 0)) : 0.f;
      v1 = (c0 + 1 < k) ? gen_normal(key0, key1, rbase + (unsigned)(c0 + 1)) : 0.f;
      v2 = (c0 + 2 < k) ? gen_normal(key0, key1, rbase + (unsigned)(c0 + 2)) : 0.f;
      v3 = (c0 + 3 < k) ? gen_normal(key0, key1, rbase + (unsigned)(c0 + 3)) : 0.f;
      INSG(fabsf(v0)) INSG(fabsf(v1)) INSG(fabsf(v2)) INSG(fabsf(v3))
      *(float4*)(Xrow + j0) = make_float4(v0, v1, v2, v3);
    }
    float* xt = xtop + (row * 4 + q) * 5;
    xt[0] = t0; xt[1] = t1; xt[2] = t2; xt[3] = t3; xt[4] = t4;
  }

  // ---- GEMM over four k-chunks of 32 rows each ----
  int lane = tid & 31;
  int warp = tid >> 5;             // 0..15
  int mtile = warp >> 1;           // 0..7 -> rows mtile*16..+15
  int nhalf = warp & 1;            // cols nhalf*64..+63
  int r0 = mtile * 16;
  int n0 = nhalf * 64;
  int g = lane >> 2;
  int t = lane & 3;

  float acc[8][4];
#pragma unroll
  for (int nt = 0; nt < 8; nt++)
#pragma unroll
    for (int j = 0; j < 4; j++) acc[nt][j] = 0.f;

  const uint32_t* Xu = (const uint32_t*)Xs;
  const uint32_t* Pu = (const uint32_t*)Ps;
  const float4* Pb4 = (const float4*)(P_padded + (size_t)b * (KMAXC * PW));
  int rA0 = r0 + g;
  int rA1 = r0 + g + 8;

  for (int c = 0; c < 4; c++) {
    int kbase = c * PROWS;
    if (kbase >= k8) break;
    int rows_this = min(PROWS, k8 - kbase);
    // stage P rows [kbase, kbase+rows_this), TF32-rounded, zero-padded
    {
      int tot = rows_this * 32;
      for (int i = tid; i < tot; i += NT) {
        int r = i >> 5, c4 = i & 31, col = c4 * 4;
        int gr = kbase + r;
        float4 v = make_float4(0.f, 0.f, 0.f, 0.f);
        if (gr < k) {
          v = Pb4[gr * 32 + c4];
          v.x = (col + 0 < nk) ? tf32_rne(v.x) : 0.f;
          v.y = (col + 1 < nk) ? tf32_rne(v.y) : 0.f;
          v.z = (col + 2 < nk) ? tf32_rne(v.z) : 0.f;
          v.w = (col + 3 < nk) ? tf32_rne(v.w) : 0.f;
        }
        *(float4*)(Ps + r * PST + col) = v;
      }
    }
    __syncthreads();   // X (c==0) + P chunk ready; prior mma reads done

    int ksteps = rows_this >> 3;
    for (int s = 0; s < ksteps; s++) {
      int kc = s * 8;           // local within chunk
      int gk = kbase + kc;      // global k col for A
      uint32_t a0 = Xu[rA0 * XST + gk + t];
      uint32_t a1 = Xu[rA1 * XST + gk + t];
      uint32_t a2 = Xu[rA0 * XST + gk + t + 4];
      uint32_t a3 = Xu[rA1 * XST + gk + t + 4];
      int pb0 = (kc + t) * PST + n0 + g;
      int pb1 = (kc + t + 4) * PST + n0 + g;
#pragma unroll
      for (int nt = 0; nt < 8; nt++) {
        uint32_t b0 = Pu[pb0 + nt * 8];
        uint32_t b1 = Pu[pb1 + nt * 8];
        mma_tf32(acc[nt], a0, a1, a2, a3, b0, b1);
      }
    }
    __syncthreads();   // mma reads done before restage / ctop aliasing
  }

  // ---- per-lane C top-5 for its two rows -> ctop (aliases dead X) ----
  {
    int slot = nhalf * 4 + t;
    { float t0 = 0.f, t1 = 0.f, t2 = 0.f, t3 = 0.f, t4 = 0.f;
#pragma unroll
      for (int nt = 0; nt < 8; nt++) { INSG(fabsf(acc[nt][0])) INSG(fabsf(acc[nt][1])) }
      float* c0p = ctop + (rA0 * 8 + slot) * 5;
      c0p[0]=t0; c0p[1]=t1; c0p[2]=t2; c0p[3]=t3; c0p[4]=t4; }
    { float t0 = 0.f, t1 = 0.f, t2 = 0.f, t3 = 0.f, t4 = 0.f;
#pragma unroll
      for (int nt = 0; nt < 8; nt++) { INSG(fabsf(acc[nt][2])) INSG(fabsf(acc[nt][3])) }
      float* c1p = ctop + (rA1 * 8 + slot) * 5;
      c1p[0]=t0; c1p[1]=t1; c1p[2]=t2; c1p[3]=t3; c1p[4]=t4; }
  }
  __syncthreads();

  // ---- merge per row (threads 0..127): 8 C-lists + 4 X-lists -> hm ----
  __shared__ float swm[4];
  if (tid < 128) {
    float t0 = 0.f, t1 = 0.f, t2 = 0.f, t3 = 0.f, t4 = 0.f;
    const float* cr = ctop + tid * 8 * 5;
#pragma unroll
    for (int j = 0; j < 40; j++) INSG(cr[j])
    const float* xr = xtop + tid * 4 * 5;
#pragma unroll
    for (int j = 0; j < 20; j++) INSG(xr[j])
    float gm = (m <= 0) ? t0 : (m == 1) ? t1 : (m == 2) ? t2
             : (m == 3) ? t3 : t4;
    float hm = t0 / (gm + 1e-9f);
    unsigned mx = __reduce_max_sync(FULLMASK, __float_as_uint(hm));
    if (lane == 0) swm[warp] = __uint_as_float(mx);
  }
  __syncthreads();
  if (tid == 0) {
    float mx = fmaxf(fmaxf(swm[0], swm[1]), fmaxf(swm[2], swm[3]));
    d_hm[b] = __float_as_uint(mx);   // single writer per b
  }
}

__global__ void final_kernel(const float* __restrict__ y_pred,
                             const float* __restrict__ y_true,
                             int B, float* __restrict__ out) {
  __shared__ float s1[512], s2[512];
  int tid = threadIdx.x;
  float a = 0.f, v = 0.f;
  for (int b = tid; b < B; b += 512) {
    float lp = log2f(fmaxf(y_pred[b], 1e-9f));
    float lt = log2f(fmaxf(y_true[b], 1e-9f));
    float d = lt - lp;
    a += d * d;
    v += fmaxf(__uint_as_float(d_hm[b]) - y_pred[b], 0.0f);
  }
  s1[tid] = a; s2[tid] = v;
  __syncthreads();
  for (int s = 256; s > 0; s >>= 1) {
    if (tid < s) { s1[tid] += s1[tid + s]; s2[tid] += s2[tid + s]; }
    __syncthreads();
  }
  if (tid == 0) {
    float logmse = s1[0] / (float)B;
    float viol   = s2[0] / (float)B;
    out[0] = logmse + 0.5f * viol;
    out[1] = logmse;
    out[2] = viol;
  }
}

extern "C" void kernel_launch(void* const* d_in, const int* in_sizes, int n_in,
                              void* d_out, int out_size) {
  const float* y_pred   = (const float*)d_in[0];
  const float* y_true   = (const float*)d_in[1];
  const float* P_padded = (const float*)d_in[2];
  const int*   params   = (const int*)d_in[3];
  float* out = (float*)d_out;
  int B = in_sizes[0];
  int stride = (in_sizes[3] >= B * 3 * 2) ? 2 : 1;   // int64 params

  int smem_bytes = SMEM_FLOATS * (int)sizeof(float);   // 95232 B
  cudaFuncSetAttribute(main_kernel,
                       cudaFuncAttributeMaxDynamicSharedMemorySize, smem_bytes);

  prep_kernel<<<1, 256>>>(params, B, stride);
  main_kernel<<<B, NT, smem_bytes>>>(P_padded, B);
  final_kernel<<<1, 512>>>(y_pred, y_true, B, out);
  (void)n_in; (void)out_size;
}